// round 2
// baseline (speedup 1.0000x reference)
#include <cuda_runtime.h>
#include <cstdint>
#include <math.h>

// Problem constants
#define BATCH   8192
#define NNODES  32
#define DIN     128
#define HID     128
#define TT      3
#define NALLY   15
#define NOPP    16

// Scratch (static __device__ allocation is allowed; cudaMalloc is not)
__device__ float g_C[BATCH * TT * DIN];   // combined vectors c_j per batch (b, j, d)
__device__ float g_u[9 * DIN];            // u[i*3+j][d] = sum_h W[i][d][h] * a_top[j][h]
__device__ float g_v[TT * DIN];           // v[j][d]     = sum_h W[j][d][h] * a_bot[j][h]
__device__ unsigned g_det;                // mask dtype classification bits

// ---------------------------------------------------------------------------
// Mask dtype detection. Element count for the bool mask is 786432 regardless of
// the on-device element width, so we classify the raw words:
//   all words in {0,1}            -> int32 bool        (mode 1)
//   all words in {0,0x3F800000}   -> float32 bool      (mode 2)
//   otherwise (packed 0/1 bytes)  -> uint8 bool        (mode 0)
// Only the first 786432 BYTES are guaranteed allocated (u8 case), so scan
// 196608 words — enough for an unambiguous answer at 40% mask density.
// ---------------------------------------------------------------------------
__global__ void kreset() { g_det = 0u; }

__global__ void kdetect(const unsigned* __restrict__ m)
{
    const int nwords = (TT * BATCH * NNODES) / 4;   // 196608
    unsigned local = 0;
    for (int i = blockIdx.x * blockDim.x + threadIdx.x; i < nwords;
         i += gridDim.x * blockDim.x) {
        unsigned w = m[i];
        if (w > 1u) local |= 1u;                            // not plain int 0/1
        if (w != 0u && w != 0x3F800000u) local |= 2u;       // not float 0/1
    }
    if (local) atomicOr(&g_det, local);
}

__device__ __forceinline__ int mask_mode_from_det(unsigned d)
{
    if (!(d & 1u)) return 1;   // int32
    if (!(d & 2u)) return 2;   // float32
    return 0;                  // uint8
}

__device__ __forceinline__ bool mask_at(const void* m, size_t idx, int mode)
{
    if (mode == 0) return ((const unsigned char*)m)[idx] != 0;
    if (mode == 1) return ((const int*)m)[idx] != 0;
    return ((const float*)m)[idx] != 0.f;
}

// ---------------------------------------------------------------------------
// k0: precompute u (9 x 128) and v (3 x 128). 12 blocks x 128 threads.
// ---------------------------------------------------------------------------
__global__ void k0_precompute(const float* __restrict__ W, const float* __restrict__ a)
{
    int vb = blockIdx.x;      // 0..8 -> u[i][j], 9..11 -> v[j]
    int d  = threadIdx.x;     // 0..127
    float acc = 0.f;
    if (vb < 9) {
        int i = vb / 3, j = vb % 3;
        const float* Wrow = W + i * (DIN * HID) + d * HID;
        const float* at   = a + j * (2 * HID);           // a_top[j][h]
        #pragma unroll 8
        for (int hh = 0; hh < HID; ++hh) acc += Wrow[hh] * at[hh];
        g_u[vb * DIN + d] = acc;
    } else {
        int j = vb - 9;
        const float* Wrow = W + j * (DIN * HID) + d * HID;
        const float* ab   = a + j * (2 * HID) + HID;     // a_bot[j][h]
        #pragma unroll 8
        for (int hh = 0; hh < HID; ++hh) acc += Wrow[hh] * ab[hh];
        g_v[j * DIN + d] = acc;
    }
}

// ---------------------------------------------------------------------------
// k1: per-batch fused scores + softmax + combine. grid=BATCH, block=160.
// ---------------------------------------------------------------------------
__device__ __forceinline__ float warp_max(float v) {
    #pragma unroll
    for (int o = 16; o; o >>= 1) v = fmaxf(v, __shfl_xor_sync(0xffffffffu, v, o));
    return v;
}
__device__ __forceinline__ float warp_sum(float v) {
    #pragma unroll
    for (int o = 16; o; o >>= 1) v += __shfl_xor_sync(0xffffffffu, v, o);
    return v;
}

__global__ __launch_bounds__(160) void k1_scores_combine(
    const float* __restrict__ h, const void* __restrict__ mask)
{
    const int b = blockIdx.x;
    const int t = threadIdx.x;              // 0..159 (5 warps)
    const int lane = t & 31, wid = t >> 5;
    const int mode = mask_mode_from_det(g_det);

    __shared__ float sh[DIN][NNODES + 1];   // transposed h_b: sh[d][node]
    __shared__ float su[10][DIN];           // u vectors (row 9 = pad)
    __shared__ float sv[DIN][4];            // v transposed: sv[d][j]
    __shared__ float s_self_s[10];          // dot(h0, u[i][j])
    __shared__ float s_nb_s[TT][NNODES];    // dot(h_n, v[j]) for nodes 1..31
    __shared__ float ex[160];
    __shared__ float wgt[TT][NNODES];       // combined softmax weights per (j,node)
    __shared__ float msks[TT];
    __shared__ float red[5];

    // ---- stage h_b (coalesced float4) into transposed smem ----
    const float4* hv = (const float4*)(h + (size_t)b * NNODES * DIN);
    for (int i = t; i < NNODES * DIN / 4; i += 160) {
        float4 vle = hv[i];
        int n  = i >> 5;            // (4*i)/128
        int d0 = (i & 31) << 2;
        sh[d0 + 0][n] = vle.x; sh[d0 + 1][n] = vle.y;
        sh[d0 + 2][n] = vle.z; sh[d0 + 3][n] = vle.w;
    }
    // stage u, v
    for (int i = t; i < 9 * DIN; i += 160) su[i / DIN][i % DIN] = g_u[i];
    for (int i = t; i < TT * DIN; i += 160) { int j = i / DIN, d = i % DIN; sv[d][j] = g_v[i]; }
    if (t < TT)
        msks[t] = mask_at(mask, (size_t)t * BATCH * NNODES + (size_t)b * NNODES + 0, mode) ? 1.f : 0.f;
    __syncthreads();

    // ---- s_self: 9 dots, 16-thread groups (group 9 clamps to 8, benign dup) ----
    {
        int g = t >> 4; if (g > 8) g = 8;
        int l = t & 15;
        float p = 0.f;
        #pragma unroll
        for (int d = l; d < DIN; d += 16) p += sh[d][0] * su[g][d];
        #pragma unroll
        for (int o = 8; o; o >>= 1) p += __shfl_down_sync(0xffffffffu, p, o, 16);
        if (l == 0) s_self_s[g] = p;
    }
    // ---- s_nb: 93 dots (node 1..31  x  j 0..2) ----
    if (t < 93) {
        int node = 1 + t / 3, j = t % 3;
        float acc = 0.f;
        #pragma unroll 8
        for (int d = 0; d < DIN; ++d) acc += sh[d][node] * sv[d][j];
        s_nb_s[j][node] = acc;
    }
    __syncthreads();

    // ---- softmax, done twice (ally: 135 entries, opp: 144) ----
    // ALLY
    {
        float e = -INFINITY;
        if (t < 135) {
            int i = t / 45, rem = t % 45, j = rem / 15, n = rem % 15;
            bool m = mask_at(mask, (size_t)j * BATCH * NNODES + (size_t)b * NNODES + (1 + n), mode);
            e = m ? -INFINITY : (s_self_s[i * 3 + j] + s_nb_s[j][1 + n]);
        }
        float wv = warp_max(e);
        if (lane == 0) red[wid] = wv;
        __syncthreads();
        float M = fmaxf(fmaxf(fmaxf(red[0], red[1]), fmaxf(red[2], red[3])), red[4]);
        __syncthreads();
        float evv = (t < 135) ? expf(e - M) : 0.f;
        ex[t] = evv;
        float ws = warp_sum(evv);
        if (lane == 0) red[wid] = ws;
        __syncthreads();
        float Z = red[0] + red[1] + red[2] + red[3] + red[4];
        if (t < 45) {
            int j = t / 15, n = t % 15;
            float w = (ex[(0 * 3 + j) * 15 + n] + ex[(1 * 3 + j) * 15 + n] + ex[(2 * 3 + j) * 15 + n]) / Z;
            wgt[j][1 + n] = w;
        }
        __syncthreads();
    }
    // OPP
    {
        float e = -INFINITY;
        if (t < 144) {
            int i = t / 48, rem = t % 48, j = rem / 16, n = rem % 16;
            bool m = mask_at(mask, (size_t)j * BATCH * NNODES + (size_t)b * NNODES + (16 + n), mode);
            e = m ? -INFINITY : (s_self_s[i * 3 + j] + s_nb_s[j][16 + n]);
        }
        float wv = warp_max(e);
        if (lane == 0) red[wid] = wv;
        __syncthreads();
        float M = fmaxf(fmaxf(fmaxf(red[0], red[1]), fmaxf(red[2], red[3])), red[4]);
        __syncthreads();
        float evv = (t < 144) ? expf(e - M) : 0.f;
        ex[t] = evv;
        float ws = warp_sum(evv);
        if (lane == 0) red[wid] = ws;
        __syncthreads();
        float Z = red[0] + red[1] + red[2] + red[3] + red[4];
        if (t < 48) {
            int j = t / 16, n = t % 16;
            float w = (ex[(0 * 3 + j) * 16 + n] + ex[(1 * 3 + j) * 16 + n] + ex[(2 * 3 + j) * 16 + n]) / Z;
            wgt[j][16 + n] = w;
        }
        __syncthreads();
    }

    // ---- combine: c_j[d] = msk_self[j]*h0[d] + sum_n wgt[j][n]*h_n[d] ----
    if (t < DIN) {
        int d = t;
        #pragma unroll
        for (int j = 0; j < TT; ++j) {
            float acc = msks[j] * sh[d][0];
            #pragma unroll
            for (int n = 1; n < NNODES; ++n) acc += wgt[j][n] * sh[d][n];
            g_C[((size_t)b * TT + j) * DIN + d] = acc;
        }
    }
}

// ---------------------------------------------------------------------------
// k2: out = elu(C @ Wstack).  M=8192, K=384, N=128. fp32 tiled GEMM.
// Wstack[k][n] == W viewed as (384,128) row-major (W is (3,128,128) row-major).
// grid = 8192/64 = 128, block = 256.
// ---------------------------------------------------------------------------
#define BM 64
#define BN 128
#define BK 32

__global__ __launch_bounds__(256) void k2_gemm_elu(
    const float* __restrict__ W, float* __restrict__ out)
{
    __shared__ float As[BK][BM + 4];
    __shared__ float Bs[BK][BN];

    const int tid = threadIdx.x;
    const int block_m = blockIdx.x * BM;
    const int tm = (tid & 15) << 2;   // 0..60
    const int tn = (tid >> 4) << 3;   // 0..120

    float acc[4][8];
    #pragma unroll
    for (int i = 0; i < 4; ++i)
        #pragma unroll
        for (int j = 0; j < 8; ++j) acc[i][j] = 0.f;

    const float* A = g_C;   // (8192 x 384) row-major

    for (int k0 = 0; k0 < TT * DIN; k0 += BK) {
        #pragma unroll
        for (int i = 0; i < 2; ++i) {
            int li = tid + i * 256;
            int r = li >> 3;                 // 0..63
            int c4 = (li & 7) << 2;          // 0..28
            float4 v = *(const float4*)&A[(size_t)(block_m + r) * (TT * DIN) + k0 + c4];
            As[c4 + 0][r] = v.x; As[c4 + 1][r] = v.y;
            As[c4 + 2][r] = v.z; As[c4 + 3][r] = v.w;
        }
        #pragma unroll
        for (int i = 0; i < 4; ++i) {
            int li = tid + i * 256;
            int r = li >> 5;                 // 0..31
            int c4 = (li & 31) << 2;         // 0..124
            *(float4*)&Bs[r][c4] = *(const float4*)&W[(size_t)(k0 + r) * BN + c4];
        }
        __syncthreads();

        #pragma unroll
        for (int k = 0; k < BK; ++k) {
            float a0[4], b0[8];
            *(float4*)a0       = *(const float4*)&As[k][tm];
            *(float4*)b0       = *(const float4*)&Bs[k][tn];
            *(float4*)(b0 + 4) = *(const float4*)&Bs[k][tn + 4];
            #pragma unroll
            for (int i = 0; i < 4; ++i)
                #pragma unroll
                for (int j = 0; j < 8; ++j) acc[i][j] += a0[i] * b0[j];
        }
        __syncthreads();
    }

    #pragma unroll
    for (int i = 0; i < 4; ++i) {
        int row = block_m + tm + i;
        #pragma unroll
        for (int j = 0; j < 8; ++j) {
            float x = acc[i][j];
            acc[i][j] = x > 0.f ? x : expm1f(x);
        }
        *(float4*)&out[(size_t)row * BN + tn]     = *(float4*)&acc[i][0];
        *(float4*)&out[(size_t)row * BN + tn + 4] = *(float4*)&acc[i][4];
    }
}

// ---------------------------------------------------------------------------
extern "C" void kernel_launch(void* const* d_in, const int* in_sizes, int n_in,
                              void* d_out, int out_size)
{
    const float* h = nullptr;
    const void*  mask = nullptr;
    const float* W = nullptr;
    const float* a = nullptr;

    for (int i = 0; i < n_in; ++i) {
        switch (in_sizes[i]) {
            case BATCH * NNODES * DIN: h    = (const float*)d_in[i]; break;   // 33554432
            case TT * BATCH * NNODES:  mask = d_in[i];               break;   // 786432
            case TT * DIN * HID:       W    = (const float*)d_in[i]; break;   // 49152
            case TT * 2 * HID:         a    = (const float*)d_in[i]; break;   // 768
            default: break; // scalar args (num_ally, num_opp, self_type)
        }
    }

    kreset<<<1, 1>>>();
    kdetect<<<64, 256>>>((const unsigned*)mask);
    k0_precompute<<<12, 128>>>(W, a);
    k1_scores_combine<<<BATCH, 160>>>(h, mask);
    k2_gemm_elu<<<BATCH / BM, 256>>>(W, (float*)d_out);
}

// round 3
// speedup vs baseline: 1.0936x; 1.0936x over previous
#include <cuda_runtime.h>
#include <cstdint>
#include <math.h>

// Problem constants
#define BATCH   8192
#define NNODES  32
#define DIN     128
#define HID     128
#define TT      3
#define NALLY   15
#define NOPP    16
#define SHP     132   // padded row stride for sh (float4-aligned, conflict-free column reads)

// Scratch (__device__ globals; cudaMalloc is forbidden)
__device__ float g_C[BATCH * TT * DIN];   // combined vectors (b, j, d)
__device__ float g_u[9 * DIN];            // u[i*3+j][d] = sum_h W[i][d][h] * a_top[j][h]
__device__ float g_v[TT * DIN];           // v[j][d]     = sum_h W[j][d][h] * a_bot[j][h]
__device__ unsigned g_det;                // mask dtype classification bits

// ---------------------------------------------------------------------------
// Mask dtype detection (single block, scans 8KB = 2048 words; unambiguous at
// 40% mask density). Modes: all words in {0,1} -> int32 (1);
// all in {0,0x3F800000} -> float32 (2); else packed bytes -> uint8 (0).
// ---------------------------------------------------------------------------
__global__ void kdetect(const unsigned* __restrict__ m)
{
    __shared__ unsigned sacc;
    if (threadIdx.x == 0) sacc = 0u;
    __syncthreads();
    unsigned local = 0;
    for (int i = threadIdx.x; i < 2048; i += 256) {
        unsigned w = m[i];
        if (w > 1u) local |= 1u;
        if (w != 0u && w != 0x3F800000u) local |= 2u;
    }
    if (local) atomicOr(&sacc, local);
    __syncthreads();
    if (threadIdx.x == 0) g_det = sacc;
}

__device__ __forceinline__ int mask_mode_from_det(unsigned d)
{
    if (!(d & 1u)) return 1;   // int32
    if (!(d & 2u)) return 2;   // float32
    return 0;                  // uint8
}

__device__ __forceinline__ bool mask_at(const void* m, size_t idx, int mode)
{
    if (mode == 0) return ((const unsigned char*)m)[idx] != 0;
    if (mode == 1) return ((const int*)m)[idx] != 0;
    return ((const float*)m)[idx] != 0.f;
}

// ---------------------------------------------------------------------------
// k0: precompute u (9 x 128) and v (3 x 128). 12 blocks x 128 threads.
// ---------------------------------------------------------------------------
__global__ void k0_precompute(const float* __restrict__ W, const float* __restrict__ a)
{
    int vb = blockIdx.x;      // 0..8 -> u[i][j], 9..11 -> v[j]
    int d  = threadIdx.x;
    float acc = 0.f;
    if (vb < 9) {
        int i = vb / 3, j = vb % 3;
        const float* Wrow = W + i * (DIN * HID) + d * HID;
        const float* at   = a + j * (2 * HID);
        #pragma unroll 8
        for (int hh = 0; hh < HID; ++hh) acc += Wrow[hh] * at[hh];
        g_u[vb * DIN + d] = acc;
    } else {
        int j = vb - 9;
        const float* Wrow = W + j * (DIN * HID) + d * HID;
        const float* ab   = a + j * (2 * HID) + HID;
        #pragma unroll 8
        for (int hh = 0; hh < HID; ++hh) acc += Wrow[hh] * ab[hh];
        g_v[j * DIN + d] = acc;
    }
}

// ---------------------------------------------------------------------------
// k1: per-batch fused load+scores+softmax+combine. grid=BATCH, block=384.
// Scores computed during the load pass: each warp-iteration covers exactly
// one node (32 lanes x float4 = 128 floats) -> butterfly-reduced dots.
// Ally & opp softmax run concurrently in disjoint thread ranges.
// 4 __syncthreads total.
// ---------------------------------------------------------------------------
__global__ __launch_bounds__(384) void k1_scores_combine(
    const float* __restrict__ h, const void* __restrict__ mask)
{
    const int b = blockIdx.x;
    const int t = threadIdx.x;
    const int lane = t & 31, wid = t >> 5;
    const int mode = mask_mode_from_det(g_det);

    __shared__ float sh[NNODES][SHP];       // h_b natural layout, padded
    __shared__ float s_self[9];             // dot(h0, u[i*3+j])
    __shared__ float s_nb[TT][NNODES];      // dot(h_n, v[j])
    __shared__ float ex[384];
    __shared__ float wgt[TT][NNODES];       // softmax weights ([j][0] = self mask)
    __shared__ float redmax[12];
    __shared__ float redsum[12];

    // ---- phase 1: load h_b + compute all dots in-flight ----
    const float4* hv = (const float4*)(h + (size_t)b * NNODES * DIN);
    #pragma unroll
    for (int k = 0; k < 3; ++k) {
        int i = t + k * 384;                // warp-uniform guard
        if (i < 1024) {
            int n  = i >> 5;                // whole warp shares one node
            int d0 = lane << 2;
            float4 val = hv[i];
            *(float4*)&sh[n][d0] = val;

            float4 v0 = *(const float4*)&g_v[0 * DIN + d0];
            float4 v1 = *(const float4*)&g_v[1 * DIN + d0];
            float4 v2 = *(const float4*)&g_v[2 * DIN + d0];
            float p0 = val.x * v0.x + val.y * v0.y + val.z * v0.z + val.w * v0.w;
            float p1 = val.x * v1.x + val.y * v1.y + val.z * v1.z + val.w * v1.w;
            float p2 = val.x * v2.x + val.y * v2.y + val.z * v2.z + val.w * v2.w;
            #pragma unroll
            for (int o = 16; o; o >>= 1) {
                p0 += __shfl_xor_sync(0xffffffffu, p0, o);
                p1 += __shfl_xor_sync(0xffffffffu, p1, o);
                p2 += __shfl_xor_sync(0xffffffffu, p2, o);
            }
            if (lane == 0) {
                s_nb[0][n] = p0; s_nb[1][n] = p1; s_nb[2][n] = p2;
            }
            if (n == 0) {   // self-node: 9 u-dots
                #pragma unroll
                for (int v = 0; v < 9; ++v) {
                    float4 uv = *(const float4*)&g_u[v * DIN + d0];
                    float q = val.x * uv.x + val.y * uv.y + val.z * uv.z + val.w * uv.w;
                    #pragma unroll
                    for (int o = 16; o; o >>= 1) q += __shfl_xor_sync(0xffffffffu, q, o);
                    if (lane == 0) s_self[v] = q;
                }
            }
        }
    }
    __syncthreads();   // B1

    // ---- phase 2: dual softmax (ally: t<135, opp: 192<=t<336) ----
    const size_t mbase = (size_t)b * NNODES;
    float e = -INFINITY;
    const bool is_ally = (t < 135);
    const bool is_opp  = (t >= 192 && t < 336);
    if (is_ally) {
        int i = t / 45, rem = t % 45, j = rem / 15, n = rem % 15;
        bool m = mask_at(mask, (size_t)j * (BATCH * NNODES) + mbase + 1 + n, mode);
        if (!m) e = s_self[i * 3 + j] + s_nb[j][1 + n];
    } else if (is_opp) {
        int local = t - 192;
        int i = local / 48, rem = local % 48, j = rem / 16, n = rem % 16;
        bool m = mask_at(mask, (size_t)j * (BATCH * NNODES) + mbase + 16 + n, mode);
        if (!m) e = s_self[i * 3 + j] + s_nb[j][16 + n];
    }
    {
        float wv = e;
        #pragma unroll
        for (int o = 16; o; o >>= 1) wv = fmaxf(wv, __shfl_xor_sync(0xffffffffu, wv, o));
        if (lane == 0) redmax[wid] = wv;
    }
    __syncthreads();   // B2

    float M;
    if (t < 192)
        M = fmaxf(fmaxf(fmaxf(redmax[0], redmax[1]), fmaxf(redmax[2], redmax[3])), redmax[4]);
    else
        M = fmaxf(fmaxf(fmaxf(redmax[6], redmax[7]), fmaxf(redmax[8], redmax[9])), redmax[10]);

    float evv = (is_ally || is_opp) ? expf(e - M) : 0.f;
    ex[t] = evv;
    {
        float ws = evv;
        #pragma unroll
        for (int o = 16; o; o >>= 1) ws += __shfl_xor_sync(0xffffffffu, ws, o);
        if (lane == 0) redsum[wid] = ws;
    }
    __syncthreads();   // B3

    // ---- weights ----
    if (t < 45) {
        float Z = redsum[0] + redsum[1] + redsum[2] + redsum[3] + redsum[4];
        int j = t / 15, n = t % 15;
        wgt[j][1 + n] = (ex[t] + ex[45 + t] + ex[90 + t]) / Z;
    } else if (t >= 192 && t < 240) {
        float Z = redsum[6] + redsum[7] + redsum[8] + redsum[9] + redsum[10];
        int local = t - 192;
        int j = local / 16, n = local % 16;
        wgt[j][16 + n] = (ex[192 + local] + ex[240 + local] + ex[288 + local]) / Z;
    } else if (t >= 336 && t < 339) {
        int j = t - 336;   // self mask -> weight on node 0
        wgt[j][0] = mask_at(mask, (size_t)j * (BATCH * NNODES) + mbase, mode) ? 1.f : 0.f;
    }
    __syncthreads();   // B4

    // ---- phase 3: combine c_j[d] = sum_n wgt[j][n] * h[n][d] ----
    {
        int j = t >> 7, d = t & 127;
        float acc0 = 0.f, acc1 = 0.f;
        #pragma unroll
        for (int n = 0; n < NNODES; n += 2) {
            acc0 += wgt[j][n]     * sh[n][d];
            acc1 += wgt[j][n + 1] * sh[n + 1][d];
        }
        g_C[(size_t)b * (TT * DIN) + t] = acc0 + acc1;
    }
}

// ---------------------------------------------------------------------------
// k2: out = elu(C @ Wstack).  M=8192, K=384, N=128. fp32 tiled GEMM.
// grid = 256 (BM=32), block = 256, 2x8 outputs/thread.
// ---------------------------------------------------------------------------
#define BM 32
#define BN 128
#define BK 32

__global__ __launch_bounds__(256) void k2_gemm_elu(
    const float* __restrict__ W, float* __restrict__ out)
{
    __shared__ float As[BK][BM + 2];
    __shared__ float Bs[BK][BN];

    const int tid = threadIdx.x;
    const int block_m = blockIdx.x * BM;
    const int tm = (tid & 15) << 1;   // 0..30
    const int tn = (tid >> 4) << 3;   // 0..120

    float acc[2][8];
    #pragma unroll
    for (int i = 0; i < 2; ++i)
        #pragma unroll
        for (int j = 0; j < 8; ++j) acc[i][j] = 0.f;

    const float* A = g_C;   // (8192 x 384) row-major

    for (int k0 = 0; k0 < TT * DIN; k0 += BK) {
        {   // A tile: 32 x 32 -> 256 float4, 1 per thread
            int r = tid >> 3;                // 0..31
            int c4 = (tid & 7) << 2;         // 0..28
            float4 v = *(const float4*)&A[(size_t)(block_m + r) * (TT * DIN) + k0 + c4];
            As[c4 + 0][r] = v.x; As[c4 + 1][r] = v.y;
            As[c4 + 2][r] = v.z; As[c4 + 3][r] = v.w;
        }
        #pragma unroll
        for (int i = 0; i < 4; ++i) {        // B tile: 32 x 128 -> 1024 float4
            int li = tid + i * 256;
            int r = li >> 5;
            int c4 = (li & 31) << 2;
            *(float4*)&Bs[r][c4] = *(const float4*)&W[(size_t)(k0 + r) * BN + c4];
        }
        __syncthreads();

        #pragma unroll
        for (int k = 0; k < BK; ++k) {
            float a0[2], b0[8];
            a0[0] = As[k][tm]; a0[1] = As[k][tm + 1];
            *(float4*)b0       = *(const float4*)&Bs[k][tn];
            *(float4*)(b0 + 4) = *(const float4*)&Bs[k][tn + 4];
            #pragma unroll
            for (int i = 0; i < 2; ++i)
                #pragma unroll
                for (int j = 0; j < 8; ++j) acc[i][j] += a0[i] * b0[j];
        }
        __syncthreads();
    }

    #pragma unroll
    for (int i = 0; i < 2; ++i) {
        int row = block_m + tm + i;
        #pragma unroll
        for (int j = 0; j < 8; ++j) {
            float x = acc[i][j];
            acc[i][j] = x > 0.f ? x : expm1f(x);
        }
        *(float4*)&out[(size_t)row * BN + tn]     = *(float4*)&acc[i][0];
        *(float4*)&out[(size_t)row * BN + tn + 4] = *(float4*)&acc[i][4];
    }
}

// ---------------------------------------------------------------------------
extern "C" void kernel_launch(void* const* d_in, const int* in_sizes, int n_in,
                              void* d_out, int out_size)
{
    const float* h = nullptr;
    const void*  mask = nullptr;
    const float* W = nullptr;
    const float* a = nullptr;

    for (int i = 0; i < n_in; ++i) {
        switch (in_sizes[i]) {
            case BATCH * NNODES * DIN: h    = (const float*)d_in[i]; break;   // 33554432
            case TT * BATCH * NNODES:  mask = d_in[i];               break;   // 786432
            case TT * DIN * HID:       W    = (const float*)d_in[i]; break;   // 49152
            case TT * 2 * HID:         a    = (const float*)d_in[i]; break;   // 768
            default: break; // scalars
        }
    }

    kdetect<<<1, 256>>>((const unsigned*)mask);
    k0_precompute<<<12, 128>>>(W, a);
    k1_scores_combine<<<BATCH, 384>>>(h, mask);
    k2_gemm_elu<<<BATCH / BM, 256>>>(W, (float*)d_out);
}

// round 5
// speedup vs baseline: 1.3661x; 1.2492x over previous
#include <cuda_runtime.h>
#include <cstdint>
#include <math.h>

// Problem constants
#define BATCH   8192
#define NNODES  32
#define DIN     128
#define HID     128
#define TT      3

// Scratch (__device__ globals; cudaMalloc is forbidden)
__device__ float g_C[BATCH * TT * DIN];   // combined vectors (b, j*128+d)
__device__ float g_u[9 * DIN];            // u[i*3+j][d] = sum_h W[i][d][h] * a_top[j][h]
__device__ float g_v[TT * DIN];           // v[j][d]     = sum_h W[j][d][h] * a_bot[j][h]
__device__ unsigned g_det;                // mask dtype classification bits

// ---------------------------------------------------------------------------
// Mask dtype helpers. Classify raw words of the bool mask buffer:
//   all words in {0,1}           -> int32 (mode 1)
//   all in {0,0x3F800000}        -> float32 (mode 2)
//   otherwise (packed 0/1 bytes) -> uint8 (mode 0)
// ---------------------------------------------------------------------------
__device__ __forceinline__ int mask_mode_from_det(unsigned d)
{
    if (!(d & 1u)) return 1;
    if (!(d & 2u)) return 2;
    return 0;
}
__device__ __forceinline__ bool mask_at(const void* m, size_t idx, int mode)
{
    if (mode == 0) return ((const unsigned char*)m)[idx] != 0;
    if (mode == 1) return ((const int*)m)[idx] != 0;
    return ((const float*)m)[idx] != 0.f;
}

// ---------------------------------------------------------------------------
// k0: precompute u (9 x 128) and v (3 x 128); block 12 does mask detection.
// 13 blocks x 128 threads.
// ---------------------------------------------------------------------------
__global__ void k0_precompute(const float* __restrict__ W, const float* __restrict__ a,
                              const unsigned* __restrict__ mraw)
{
    int vb = blockIdx.x;
    int d  = threadIdx.x;
    if (vb == 12) {   // mask dtype detection: scan first 8KB (2048 words)
        __shared__ unsigned sacc;
        if (d == 0) sacc = 0u;
        __syncthreads();
        unsigned local = 0;
        for (int i = d; i < 2048; i += 128) {
            unsigned w = mraw[i];
            if (w > 1u) local |= 1u;
            if (w != 0u && w != 0x3F800000u) local |= 2u;
        }
        if (local) atomicOr(&sacc, local);
        __syncthreads();
        if (d == 0) g_det = sacc;
        return;
    }
    float acc = 0.f;
    if (vb < 9) {
        int i = vb / 3, j = vb % 3;
        const float* Wrow = W + i * (DIN * HID) + d * HID;
        const float* at   = a + j * (2 * HID);
        #pragma unroll 8
        for (int hh = 0; hh < HID; ++hh) acc += Wrow[hh] * at[hh];
        g_u[vb * DIN + d] = acc;
    } else {
        int j = vb - 9;
        const float* Wrow = W + j * (DIN * HID) + d * HID;
        const float* ab   = a + j * (2 * HID) + HID;
        #pragma unroll 8
        for (int hh = 0; hh < HID; ++hh) acc += Wrow[hh] * ab[hh];
        g_v[j * DIN + d] = acc;
    }
}

// ---------------------------------------------------------------------------
// k1: one WARP per batch. Zero __syncthreads; single __syncwarp.
// 4 warps/CTA, grid = 2048, dynamic smem = 4 * (32*128 + 128) floats.
// ---------------------------------------------------------------------------
#define K1_WARPS 4
#define WSLOT    (NNODES * DIN + 128)   // per-warp smem floats (h tile + weights)

__device__ __forceinline__ float dot4(float4 x, float4 y)
{ return x.x * y.x + x.y * y.y + x.z * y.z + x.w * y.w; }

__global__ __launch_bounds__(32 * K1_WARPS) void k1_scores_combine(
    const float* __restrict__ h, const void* __restrict__ mask)
{
    extern __shared__ float smem[];
    const int lane = threadIdx.x & 31;
    const int w    = threadIdx.x >> 5;
    const int b    = blockIdx.x * K1_WARPS + w;
    const int mode = mask_mode_from_det(g_det);
    float* sh = smem + w * WSLOT;            // [32 nodes][128]
    float* sw = sh + NNODES * DIN;           // [3][32] weights

    const int d4 = lane << 2;
    const float4 v0 = *(const float4*)&g_v[0 * DIN + d4];
    const float4 v1 = *(const float4*)&g_v[1 * DIN + d4];
    const float4 v2 = *(const float4*)&g_v[2 * DIN + d4];

    const float4* hv = (const float4*)(h + (size_t)b * NNODES * DIN);

    // ---- node 0 (self): load + 9 u-dots ----
    float4 val = hv[lane];
    *(float4*)&sh[d4] = val;
    float s_self[9];
    #pragma unroll
    for (int u = 0; u < 9; ++u) {
        float4 uv = *(const float4*)&g_u[u * DIN + d4];
        float q = dot4(val, uv);
        #pragma unroll
        for (int o = 16; o; o >>= 1) q += __shfl_xor_sync(0xffffffffu, q, o);
        s_self[u] = q;
    }

    // ---- nodes 1..31: load + 3 v-dots; lane n keeps s_nb[:,n] ----
    float r0 = 0.f, r1 = 0.f, r2 = 0.f;
    #pragma unroll 4
    for (int it = 1; it < NNODES; ++it) {
        val = hv[(it << 5) + lane];
        *(float4*)&sh[(it << 7) + d4] = val;
        float p0 = dot4(val, v0);
        float p1 = dot4(val, v1);
        float p2 = dot4(val, v2);
        #pragma unroll
        for (int o = 16; o; o >>= 1) {
            p0 += __shfl_xor_sync(0xffffffffu, p0, o);
            p1 += __shfl_xor_sync(0xffffffffu, p1, o);
            p2 += __shfl_xor_sync(0xffffffffu, p2, o);
        }
        if (lane == it) { r0 = p0; r1 = p1; r2 = p2; }
    }

    // ---- masks for this lane's node ----
    const size_t mstr = (size_t)BATCH * NNODES;
    const size_t mb   = (size_t)b * NNODES + lane;
    const bool m0 = mask_at(mask, 0 * mstr + mb, mode);
    const bool m1 = mask_at(mask, 1 * mstr + mb, mode);
    const bool m2 = mask_at(mask, 2 * mstr + mb, mode);

    // ---- dual softmax, register-resident.
    // Lanes 1..15 = ally nodes, 16..31 = opp nodes (16-wide halves).
    // Lane 0 contributes -inf (node 0 is in neither softmax).
    const float eb0 = (m0 || lane == 0) ? -INFINITY : r0;
    const float eb1 = (m1 || lane == 0) ? -INFINITY : r1;
    const float eb2 = (m2 || lane == 0) ? -INFINITY : r2;

    float mx = -INFINITY;
    #pragma unroll
    for (int i = 0; i < 3; ++i) {
        mx = fmaxf(mx, s_self[i * 3 + 0] + eb0);
        mx = fmaxf(mx, s_self[i * 3 + 1] + eb1);
        mx = fmaxf(mx, s_self[i * 3 + 2] + eb2);
    }
    #pragma unroll
    for (int o = 8; o; o >>= 1) mx = fmaxf(mx, __shfl_xor_sync(0xffffffffu, mx, o));

    float s0 = 0.f, s1 = 0.f, s2 = 0.f;
    #pragma unroll
    for (int i = 0; i < 3; ++i) {
        s0 += __expf(s_self[i * 3 + 0] + eb0 - mx);
        s1 += __expf(s_self[i * 3 + 1] + eb1 - mx);
        s2 += __expf(s_self[i * 3 + 2] + eb2 - mx);
    }
    float zs = s0 + s1 + s2;
    #pragma unroll
    for (int o = 8; o; o >>= 1) zs += __shfl_xor_sync(0xffffffffu, zs, o);
    // NaN (all-masked half) -> (zs>0) false -> weights 0, matching reference.
    const float inv = (zs > 0.f) ? (1.f / zs) : 0.f;

    // self-node weight = mask_self (multiplicative 1/0), per reference
    sw[0 * 32 + lane] = (lane == 0) ? (m0 ? 1.f : 0.f) : s0 * inv;
    sw[1 * 32 + lane] = (lane == 0) ? (m1 ? 1.f : 0.f) : s1 * inv;
    sw[2 * 32 + lane] = (lane == 0) ? (m2 ? 1.f : 0.f) : s2 * inv;
    __syncwarp();

    // ---- combine: c_j[d] = sum_n w[j][n] * h[n][d] ----
    float* gout = g_C + (size_t)b * (TT * DIN);
    #pragma unroll
    for (int j = 0; j < TT; ++j) {
        float ax = 0.f, ay = 0.f, az = 0.f, aw = 0.f;
        #pragma unroll
        for (int n = 0; n < NNODES; ++n) {
            float wv = sw[j * 32 + n];
            float4 hn = *(const float4*)&sh[(n << 7) + d4];
            ax += wv * hn.x; ay += wv * hn.y; az += wv * hn.z; aw += wv * hn.w;
        }
        float4 o4 = {ax, ay, az, aw};
        *(float4*)&gout[j * DIN + d4] = o4;
    }
}

// ---------------------------------------------------------------------------
// k2: out = elu(C @ Wstack). M=8192, K=384, N=128. fp32 with packed FFMA2.
// BM=64, BN=64, BK=64; block=128; grid=(128,2). Per-thread 4(M,strided)x8(N).
// ---------------------------------------------------------------------------
#define GBM 64
#define GBN 64
#define GBK 64
#define APAD 3   // As row stride 67 -> 2-way max bank conflicts

#define FMA_F32X2(d, a, bb, c) \
    asm("fma.rn.f32x2 %0, %1, %2, %3;" : "=l"(d) : "l"(a), "l"(bb), "l"(c))
#define PACK_DUP(d, s) \
    asm("mov.b64 %0, {%1, %1};" : "=l"(d) : "r"(s))

__global__ __launch_bounds__(128) void k2_gemm_elu(
    const float* __restrict__ W, float* __restrict__ out)
{
    __shared__ float As[GBK][GBM + APAD];   // [k][m]
    __shared__ float Bs[GBK][GBN];          // [k][n]

    const int tid = threadIdx.x;
    const int bm0 = blockIdx.x * GBM;
    const int bn0 = blockIdx.y * GBN;
    const int tm0 = tid & 15;               // m = tm0 + 16*mi
    const int tn  = (tid >> 4) << 3;        // 0..56

    unsigned long long acc[4][4];           // [mi][n-pair]; 0ull == {0f,0f}
    #pragma unroll
    for (int i = 0; i < 4; ++i)
        #pragma unroll
        for (int j = 0; j < 4; ++j) acc[i][j] = 0ull;

    const float* A = g_C;

    for (int k0 = 0; k0 < TT * DIN; k0 += GBK) {
        // A tile: 64x64, transpose into As[k][m]
        #pragma unroll
        for (int i = 0; i < 8; ++i) {
            int li = tid + i * 128;
            int r  = li >> 4;                // m row 0..63
            int c4 = (li & 15) << 2;         // k col 0..60
            float4 v = *(const float4*)&A[(size_t)(bm0 + r) * (TT * DIN) + k0 + c4];
            As[c4 + 0][r] = v.x; As[c4 + 1][r] = v.y;
            As[c4 + 2][r] = v.z; As[c4 + 3][r] = v.w;
        }
        // B tile: 64x64 natural layout (W is (384,128) row-major)
        #pragma unroll
        for (int i = 0; i < 8; ++i) {
            int li = tid + i * 128;
            int r  = li >> 4;                // k row 0..63
            int c4 = (li & 15) << 2;         // n col 0..60
            *(float4*)&Bs[r][c4] = *(const float4*)&W[(size_t)(k0 + r) * DIN + bn0 + c4];
        }
        __syncthreads();

        #pragma unroll 8
        for (int kk = 0; kk < GBK; ++kk) {
            unsigned long long ad[4];
            PACK_DUP(ad[0], __float_as_uint(As[kk][tm0]));
            PACK_DUP(ad[1], __float_as_uint(As[kk][tm0 + 16]));
            PACK_DUP(ad[2], __float_as_uint(As[kk][tm0 + 32]));
            PACK_DUP(ad[3], __float_as_uint(As[kk][tm0 + 48]));
            ulonglong2 b01 = *(const ulonglong2*)&Bs[kk][tn];
            ulonglong2 b23 = *(const ulonglong2*)&Bs[kk][tn + 4];
            unsigned long long bv[4] = {b01.x, b01.y, b23.x, b23.y};
            #pragma unroll
            for (int mi = 0; mi < 4; ++mi)
                #pragma unroll
                for (int jj = 0; jj < 4; ++jj)
                    FMA_F32X2(acc[mi][jj], ad[mi], bv[jj], acc[mi][jj]);
        }
        __syncthreads();
    }

    // epilogue: unpack, ELU, store
    #pragma unroll
    for (int mi = 0; mi < 4; ++mi) {
        int m = bm0 + tm0 + 16 * mi;
        float o8[8];
        #pragma unroll
        for (int jj = 0; jj < 4; ++jj) {
            unsigned long long p = acc[mi][jj];
            o8[2 * jj]     = __uint_as_float((unsigned)(p & 0xffffffffull));
            o8[2 * jj + 1] = __uint_as_float((unsigned)(p >> 32));
        }
        #pragma unroll
        for (int q = 0; q < 8; ++q) {
            float x = o8[q];
            o8[q] = x > 0.f ? x : expm1f(x);
        }
        *(float4*)&out[(size_t)m * DIN + bn0 + tn]     = *(float4*)&o8[0];
        *(float4*)&out[(size_t)m * DIN + bn0 + tn + 4] = *(float4*)&o8[4];
    }
}

// ---------------------------------------------------------------------------
extern "C" void kernel_launch(void* const* d_in, const int* in_sizes, int n_in,
                              void* d_out, int out_size)
{
    const float* h = nullptr;
    const void*  mask = nullptr;
    const float* W = nullptr;
    const float* a = nullptr;

    for (int i = 0; i < n_in; ++i) {
        switch (in_sizes[i]) {
            case BATCH * NNODES * DIN: h    = (const float*)d_in[i]; break;   // 33554432
            case TT * BATCH * NNODES:  mask = d_in[i];               break;   // 786432
            case TT * DIN * HID:       W    = (const float*)d_in[i]; break;   // 49152
            case TT * 2 * HID:         a    = (const float*)d_in[i]; break;   // 768
            default: break; // scalars
        }
    }

    const int k1_smem = K1_WARPS * WSLOT * (int)sizeof(float);   // 67.6 KB
    cudaFuncSetAttribute(k1_scores_combine,
                         cudaFuncAttributeMaxDynamicSharedMemorySize, k1_smem);

    k0_precompute<<<13, 128>>>(W, a, (const unsigned*)mask);
    k1_scores_combine<<<BATCH / K1_WARPS, 32 * K1_WARPS, k1_smem>>>(h, mask);
    k2_gemm_elu<<<dim3(BATCH / GBM, DIN / GBN), 128>>>(W, (float*)d_out);
}

// round 7
// speedup vs baseline: 1.3715x; 1.0039x over previous
#include <cuda_runtime.h>
#include <cstdint>
#include <math.h>

// Problem constants
#define BATCH   8192
#define NNODES  32
#define DIN     128
#define HID     128
#define TT      3

// Scratch (__device__ globals; cudaMalloc is forbidden)
__device__ float g_C[BATCH * TT * DIN];   // combined vectors (b, j*128+d)
__device__ float g_u[9 * DIN];            // u[i*3+j][d] = sum_h W[i][d][h] * a_top[j][h]
__device__ float g_v[TT * DIN];           // v[j][d]     = sum_h W[j][d][h] * a_bot[j][h]
__device__ unsigned g_det;                // mask dtype classification bits

// ---------------------------------------------------------------------------
// Mask dtype helpers (bool buffer may be u8 / i32 / f32 on device).
// ---------------------------------------------------------------------------
__device__ __forceinline__ int mask_mode_from_det(unsigned d)
{
    if (!(d & 1u)) return 1;   // int32
    if (!(d & 2u)) return 2;   // float32
    return 0;                  // uint8
}
__device__ __forceinline__ bool mask_at(const void* m, size_t idx, int mode)
{
    if (mode == 0) return ((const unsigned char*)m)[idx] != 0;
    if (mode == 1) return ((const int*)m)[idx] != 0;
    return ((const float*)m)[idx] != 0.f;
}

__device__ __forceinline__ float dot4(float4 x, float4 y)
{ return x.x * y.x + x.y * y.y + x.z * y.z + x.w * y.w; }

// ---------------------------------------------------------------------------
// k0: warp-per-dot precompute of u (9x128) and v (3x128) = 1536 dots.
// Blocks 0..383: 4 warps each, one dot per warp (2 coalesced LDG.128 + butterfly).
// Block 384: mask dtype detection.
// ---------------------------------------------------------------------------
__global__ __launch_bounds__(128) void k0_precompute(
    const float* __restrict__ W, const float* __restrict__ a,
    const unsigned* __restrict__ mraw)
{
    if (blockIdx.x == 384) {   // detection: scan first 8KB (2048 words)
        __shared__ unsigned sacc;
        int t = threadIdx.x;
        if (t == 0) sacc = 0u;
        __syncthreads();
        unsigned local = 0;
        for (int i = t; i < 2048; i += 128) {
            unsigned w = mraw[i];
            if (w > 1u) local |= 1u;
            if (w != 0u && w != 0x3F800000u) local |= 2u;
        }
        if (local) atomicOr(&sacc, local);
        __syncthreads();
        if (t == 0) g_det = sacc;
        return;
    }
    const int lane = threadIdx.x & 31;
    const int g = blockIdx.x * 4 + (threadIdx.x >> 5);   // dot id 0..1535
    const int vb = g >> 7;        // 0..11
    const int d  = g & 127;
    float q;
    if (vb < 9) {
        int i = vb / 3, j = vb % 3;
        float4 wv = *(const float4*)&W[(size_t)i * (DIN * HID) + d * HID + (lane << 2)];
        float4 av = *(const float4*)&a[j * (2 * HID) + (lane << 2)];
        q = dot4(wv, av);
    } else {
        int j = vb - 9;
        float4 wv = *(const float4*)&W[(size_t)j * (DIN * HID) + d * HID + (lane << 2)];
        float4 av = *(const float4*)&a[j * (2 * HID) + HID + (lane << 2)];
        q = dot4(wv, av);
    }
    #pragma unroll
    for (int o = 16; o; o >>= 1) q += __shfl_xor_sync(0xffffffffu, q, o);
    if (lane == 0) {
        if (vb < 9) g_u[vb * DIN + d] = q;
        else        g_v[(vb - 9) * DIN + d] = q;
    }
}

// ---------------------------------------------------------------------------
// k1: one WARP per batch, zero __syncthreads, ~25 shfl total.
// Lane n owns node n: dots computed in-lane from smem rows (conflict-free).
// 4 warps/CTA, grid = 2048.
// ---------------------------------------------------------------------------
#define K1_WARPS 4
#define WROW  132                       // padded row stride (4n mod 32 banks)
#define WSLOT (NNODES * WROW + 96)      // + weights [3][32]

__global__ __launch_bounds__(32 * K1_WARPS) void k1_scores_combine(
    const float* __restrict__ h, const void* __restrict__ mask)
{
    extern __shared__ float smem[];
    const int lane = threadIdx.x & 31;
    const int w    = threadIdx.x >> 5;
    const int b    = blockIdx.x * K1_WARPS + w;
    const int mode = mask_mode_from_det(g_det);
    float* sh = smem + w * WSLOT;            // [32 nodes][132]
    float* sw = sh + NNODES * WROW;          // [3][32] weights

    const int d4 = lane << 2;
    const float4* hv = (const float4*)(h + (size_t)b * NNODES * DIN);

    // ---- phase A: pure coalesced load (high MLP, no dependent math) ----
    #pragma unroll
    for (int it = 0; it < NNODES; ++it) {
        float4 val = hv[(it << 5) + lane];
        *(float4*)&sh[it * WROW + d4] = val;
    }
    __syncwarp();

    // ---- phase B: lane n computes s_nb[j][n] from its own smem row ----
    float r0a = 0.f, r0b = 0.f, r1a = 0.f, r1b = 0.f, r2a = 0.f, r2b = 0.f;
    const float* row = sh + lane * WROW;
    #pragma unroll 8
    for (int c = 0; c < 32; ++c) {
        float4 x  = *(const float4*)&row[c << 2];
        float4 w0 = *(const float4*)&g_v[0 * DIN + (c << 2)];   // broadcast, L1-hot
        float4 w1 = *(const float4*)&g_v[1 * DIN + (c << 2)];
        float4 w2 = *(const float4*)&g_v[2 * DIN + (c << 2)];
        float p0 = dot4(x, w0), p1 = dot4(x, w1), p2 = dot4(x, w2);
        if (c & 1) { r0b += p0; r1b += p1; r2b += p2; }
        else       { r0a += p0; r1a += p1; r2a += p2; }
    }
    const float r0 = r0a + r0b, r1 = r1a + r1b, r2 = r2a + r2b;

    // ---- lanes 0..8: the 9 s_self dots (read node-0 row, broadcast) ----
    float sself = 0.f;
    if (lane < 9) {
        float q0 = 0.f, q1 = 0.f;
        const float* uvec = g_u + lane * DIN;
        #pragma unroll 8
        for (int c = 0; c < 32; ++c) {
            float4 x  = *(const float4*)&sh[c << 2];            // row 0
            float4 uu = *(const float4*)&uvec[c << 2];
            float p = dot4(x, uu);
            if (c & 1) q1 += p; else q0 += p;
        }
        sself = q0 + q1;
    }
    float ss[9];
    #pragma unroll
    for (int k = 0; k < 9; ++k) ss[k] = __shfl_sync(0xffffffffu, sself, k);

    // ---- masks for this lane's node ----
    const size_t mstr = (size_t)BATCH * NNODES;
    const size_t mb   = (size_t)b * NNODES + lane;
    const bool m0 = mask_at(mask, 0 * mstr + mb, mode);
    const bool m1 = mask_at(mask, 1 * mstr + mb, mode);
    const bool m2 = mask_at(mask, 2 * mstr + mb, mode);

    // ---- dual register-resident softmax (lanes 1..15 ally, 16..31 opp) ----
    const float eb0 = (m0 || lane == 0) ? -INFINITY : r0;
    const float eb1 = (m1 || lane == 0) ? -INFINITY : r1;
    const float eb2 = (m2 || lane == 0) ? -INFINITY : r2;

    float mx = -INFINITY;
    #pragma unroll
    for (int i = 0; i < 3; ++i) {
        mx = fmaxf(mx, ss[i * 3 + 0] + eb0);
        mx = fmaxf(mx, ss[i * 3 + 1] + eb1);
        mx = fmaxf(mx, ss[i * 3 + 2] + eb2);
    }
    #pragma unroll
    for (int o = 8; o; o >>= 1) mx = fmaxf(mx, __shfl_xor_sync(0xffffffffu, mx, o));

    float s0 = 0.f, s1 = 0.f, s2 = 0.f;
    #pragma unroll
    for (int i = 0; i < 3; ++i) {
        s0 += __expf(ss[i * 3 + 0] + eb0 - mx);
        s1 += __expf(ss[i * 3 + 1] + eb1 - mx);
        s2 += __expf(ss[i * 3 + 2] + eb2 - mx);
    }
    float zs = s0 + s1 + s2;
    #pragma unroll
    for (int o = 8; o; o >>= 1) zs += __shfl_xor_sync(0xffffffffu, zs, o);
    // all-masked half -> zs NaN -> inv 0 -> weights 0 (matches reference)
    const float inv = (zs > 0.f) ? (1.f / zs) : 0.f;

    sw[0 * 32 + lane] = (lane == 0) ? (m0 ? 1.f : 0.f) : s0 * inv;
    sw[1 * 32 + lane] = (lane == 0) ? (m1 ? 1.f : 0.f) : s1 * inv;
    sw[2 * 32 + lane] = (lane == 0) ? (m2 ? 1.f : 0.f) : s2 * inv;
    __syncwarp();

    // ---- combine: read each h-row once, FMA into 3 accumulators ----
    float4 a0 = {0.f, 0.f, 0.f, 0.f}, a1 = a0, a2 = a0;
    #pragma unroll
    for (int n = 0; n < NNODES; ++n) {
        float4 x = *(const float4*)&sh[n * WROW + d4];
        float w0 = sw[n], w1 = sw[32 + n], w2 = sw[64 + n];
        a0.x += w0 * x.x; a0.y += w0 * x.y; a0.z += w0 * x.z; a0.w += w0 * x.w;
        a1.x += w1 * x.x; a1.y += w1 * x.y; a1.z += w1 * x.z; a1.w += w1 * x.w;
        a2.x += w2 * x.x; a2.y += w2 * x.y; a2.z += w2 * x.z; a2.w += w2 * x.w;
    }
    float* gout = g_C + (size_t)b * (TT * DIN);
    *(float4*)&gout[0 * DIN + d4] = a0;
    *(float4*)&gout[1 * DIN + d4] = a1;
    *(float4*)&gout[2 * DIN + d4] = a2;
}

// ---------------------------------------------------------------------------
// k2: out = elu(C @ Wstack). M=8192, K=384, N=128. fp32 packed FFMA2.
// BM=BN=BK=64; block=256; grid=(128,2). Per-thread 2(M)x8(N).
// ---------------------------------------------------------------------------
#define GBM 64
#define GBN 64
#define GBK 64
#define APAD 3

#define FMA_F32X2(d, a, bb, c) \
    asm("fma.rn.f32x2 %0, %1, %2, %3;" : "=l"(d) : "l"(a), "l"(bb), "l"(c))
#define PACK_DUP(d, s) \
    asm("mov.b64 %0, {%1, %1};" : "=l"(d) : "r"(s))

__global__ __launch_bounds__(256) void k2_gemm_elu(
    const float* __restrict__ W, float* __restrict__ out)
{
    __shared__ float As[GBK][GBM + APAD];   // [k][m]
    __shared__ float Bs[GBK][GBN];          // [k][n]

    const int tid = threadIdx.x;
    const int bm0 = blockIdx.x * GBM;
    const int bn0 = blockIdx.y * GBN;
    const int tm0 = tid & 31;               // m = tm0 + 32*mi
    const int tn  = (tid >> 5) << 3;        // warp-uniform, 0..56

    unsigned long long acc[2][4];
    #pragma unroll
    for (int i = 0; i < 2; ++i)
        #pragma unroll
        for (int j = 0; j < 4; ++j) acc[i][j] = 0ull;

    const float* A = g_C;

    for (int k0 = 0; k0 < TT * DIN; k0 += GBK) {
        #pragma unroll
        for (int i = 0; i < 4; ++i) {       // A tile 64x64 -> transpose to As[k][m]
            int li = tid + i * 256;
            int r  = li >> 4;                // m row 0..63
            int c4 = (li & 15) << 2;         // k col 0..60
            float4 v = *(const float4*)&A[(size_t)(bm0 + r) * (TT * DIN) + k0 + c4];
            As[c4 + 0][r] = v.x; As[c4 + 1][r] = v.y;
            As[c4 + 2][r] = v.z; As[c4 + 3][r] = v.w;
        }
        #pragma unroll
        for (int i = 0; i < 4; ++i) {       // B tile 64x64 natural
            int li = tid + i * 256;
            int r  = li >> 4;
            int c4 = (li & 15) << 2;
            *(float4*)&Bs[r][c4] = *(const float4*)&W[(size_t)(k0 + r) * DIN + bn0 + c4];
        }
        __syncthreads();

        #pragma unroll 8
        for (int kk = 0; kk < GBK; ++kk) {
            unsigned long long ad[2];
            PACK_DUP(ad[0], __float_as_uint(As[kk][tm0]));
            PACK_DUP(ad[1], __float_as_uint(As[kk][tm0 + 32]));
            ulonglong2 b01 = *(const ulonglong2*)&Bs[kk][tn];      // warp-broadcast
            ulonglong2 b23 = *(const ulonglong2*)&Bs[kk][tn + 4];
            unsigned long long bv[4] = {b01.x, b01.y, b23.x, b23.y};
            #pragma unroll
            for (int mi = 0; mi < 2; ++mi)
                #pragma unroll
                for (int jj = 0; jj < 4; ++jj)
                    FMA_F32X2(acc[mi][jj], ad[mi], bv[jj], acc[mi][jj]);
        }
        __syncthreads();
    }

    #pragma unroll
    for (int mi = 0; mi < 2; ++mi) {
        int m = bm0 + tm0 + 32 * mi;
        float o8[8];
        #pragma unroll
        for (int jj = 0; jj < 4; ++jj) {
            unsigned long long p = acc[mi][jj];
            o8[2 * jj]     = __uint_as_float((unsigned)(p & 0xffffffffull));
            o8[2 * jj + 1] = __uint_as_float((unsigned)(p >> 32));
        }
        #pragma unroll
        for (int q = 0; q < 8; ++q) {
            float x = o8[q];
            o8[q] = x > 0.f ? x : expm1f(x);
        }
        *(float4*)&out[(size_t)m * DIN + bn0 + tn]     = *(float4*)&o8[0];
        *(float4*)&out[(size_t)m * DIN + bn0 + tn + 4] = *(float4*)&o8[4];
    }
}

// ---------------------------------------------------------------------------
extern "C" void kernel_launch(void* const* d_in, const int* in_sizes, int n_in,
                              void* d_out, int out_size)
{
    const float* h = nullptr;
    const void*  mask = nullptr;
    const float* W = nullptr;
    const float* a = nullptr;

    for (int i = 0; i < n_in; ++i) {
        switch (in_sizes[i]) {
            case BATCH * NNODES * DIN: h    = (const float*)d_in[i]; break;   // 33554432
            case TT * BATCH * NNODES:  mask = d_in[i];               break;   // 786432
            case TT * DIN * HID:       W    = (const float*)d_in[i]; break;   // 49152
            case TT * 2 * HID:         a    = (const float*)d_in[i]; break;   // 768
            default: break; // scalars
        }
    }

    const int k1_smem = K1_WARPS * WSLOT * (int)sizeof(float);   // 67.9 KB
    cudaFuncSetAttribute(k1_scores_combine,
                         cudaFuncAttributeMaxDynamicSharedMemorySize, k1_smem);

    k0_precompute<<<385, 128>>>(W, a, (const unsigned*)mask);
    k1_scores_combine<<<BATCH / K1_WARPS, 32 * K1_WARPS, k1_smem>>>(h, mask);
    k2_gemm_elu<<<dim3(BATCH / GBM, DIN / GBN), 256>>>(W, (float*)d_out);
}

// round 9
// speedup vs baseline: 1.8363x; 1.3390x over previous
#include <cuda_runtime.h>
#include <cstdint>
#include <math.h>

// Problem constants
#define BATCH   8192
#define NNODES  32
#define DIN     128
#define HID     128
#define TT      3

// Scratch (__device__ globals; cudaMalloc is forbidden)
__device__ float g_C[BATCH * TT * DIN];   // combined vectors (b, j*128+d)
__device__ float g_u[9 * DIN];            // u[i*3+j][d] = sum_h W[i][d][h]*a_top[j][h]
__device__ float g_v[TT * DIN];           // v[j][d]     = sum_h W[j][d][h]*a_bot[j][h]
__device__ unsigned g_det;                // mask dtype classification bits

// ---------------------------------------------------------------------------
// Mask dtype helpers (bool buffer may be u8 / i32 / f32 on device).
// ---------------------------------------------------------------------------
__device__ __forceinline__ int mask_mode_from_det(unsigned d)
{
    if (!(d & 1u)) return 1;   // int32
    if (!(d & 2u)) return 2;   // float32
    return 0;                  // uint8
}
__device__ __forceinline__ bool mask_at(const void* m, size_t idx, int mode)
{
    if (mode == 0) return ((const unsigned char*)m)[idx] != 0;
    if (mode == 1) return ((const int*)m)[idx] != 0;
    return ((const float*)m)[idx] != 0.f;
}

__device__ __forceinline__ float dot4(float4 x, float4 y)
{ return x.x * y.x + x.y * y.y + x.z * y.z + x.w * y.w; }

// ---------------------------------------------------------------------------
// k0: 4 dots per warp (MLP=8). 1536 dots -> 384 warps -> 48 blocks x 256.
// Block 48 does mask dtype detection.
// ---------------------------------------------------------------------------
__global__ __launch_bounds__(256) void k0_precompute(
    const float* __restrict__ W, const float* __restrict__ a,
    const unsigned* __restrict__ mraw)
{
    if (blockIdx.x == 48) {   // detection: scan first 8KB (2048 words)
        __shared__ unsigned sacc;
        int t = threadIdx.x;
        if (t == 0) sacc = 0u;
        __syncthreads();
        unsigned local = 0;
        for (int i = t; i < 2048; i += 256) {
            unsigned w = mraw[i];
            if (w > 1u) local |= 1u;
            if (w != 0u && w != 0x3F800000u) local |= 2u;
        }
        if (local) atomicOr(&sacc, local);
        __syncthreads();
        if (t == 0) g_det = sacc;
        return;
    }
    const int lane = threadIdx.x & 31;
    const int wg   = blockIdx.x * 8 + (threadIdx.x >> 5);   // 0..383
    const int base = wg * 4;                                // dot ids base..base+3
    const int vb   = base >> 7;                             // 0..11 (const across 4)
    const int d0   = base & 127;

    const float* Wbase;
    const float* avec;
    if (vb < 9) {
        Wbase = W + (size_t)(vb / 3) * (DIN * HID);
        avec  = a + (vb % 3) * (2 * HID);
    } else {
        Wbase = W + (size_t)(vb - 9) * (DIN * HID);
        avec  = a + (vb - 9) * (2 * HID) + HID;
    }
    float4 av = *(const float4*)&avec[lane << 2];

    float acc[4];
    #pragma unroll
    for (int r = 0; r < 4; ++r) {
        float4 wv = *(const float4*)&Wbase[(size_t)(d0 + r) * HID + (lane << 2)];
        acc[r] = dot4(wv, av);
    }
    #pragma unroll
    for (int o = 16; o; o >>= 1)
        #pragma unroll
        for (int r = 0; r < 4; ++r)
            acc[r] += __shfl_xor_sync(0xffffffffu, acc[r], o);
    if (lane == 0) {
        float4 res = {acc[0], acc[1], acc[2], acc[3]};
        if (vb < 9) *(float4*)&g_u[vb * DIN + d0] = res;
        else        *(float4*)&g_v[(vb - 9) * DIN + d0] = res;
    }
}

// ---------------------------------------------------------------------------
// k1-lite: one WARP per batch, ~900B smem/warp (no h staging).
// Dot phase: 8-lane groups own quarter-rows, 4 nodes per warp-iteration,
// coalesced loads, 3-stage group butterflies. Combine re-reads h (L1/L2 hot).
// 8 warps/CTA, grid=1024, __launch_bounds__(256,3) -> 24 warps/SM.
// ---------------------------------------------------------------------------
#define K1_WARPS 8
#define WSL      224   // per-warp smem floats: nb[3][32] + ss[16] + wt[3][32] + pad

__global__ __launch_bounds__(256, 3) void k1_scores_combine(
    const float* __restrict__ h, const void* __restrict__ mask)
{
    __shared__ float smem[K1_WARPS * WSL];
    const int lane = threadIdx.x & 31;
    const int w    = threadIdx.x >> 5;
    const int b    = blockIdx.x * K1_WARPS + w;
    const int mode = mask_mode_from_det(g_det);
    float* snb = smem + w * WSL;     // [3][32] neighbor scores
    float* sss = snb + 96;           // [9] self scores (+pad)
    float* swt = sss + 16;           // [3][32] weights

    const int g = lane >> 3;         // group 0..3 (node within 4-pack)
    const int q = lane & 7;          // quarter position 0..7

    const float* hb = h + (size_t)b * NNODES * DIN;

    // ---- masks early (hide latency under dot phase) ----
    const size_t mstr = (size_t)BATCH * NNODES;
    const size_t mb   = (size_t)b * NNODES + lane;
    const bool m0 = mask_at(mask, 0 * mstr + mb, mode);
    const bool m1 = mask_at(mask, 1 * mstr + mb, mode);
    const bool m2 = mask_at(mask, 2 * mstr + mb, mode);

    // ---- dot phase: 8 iterations x 4 nodes ----
    #pragma unroll
    for (int it = 0; it < 8; ++it) {
        const int node = (it << 2) + g;
        const float4* rowp = (const float4*)(hb + node * DIN);
        float p0 = 0.f, p1 = 0.f, p2 = 0.f;
        #pragma unroll
        for (int k = 0; k < 4; ++k) {
            float4 x  = rowp[q + (k << 3)];
            float4 v0 = *(const float4*)&g_v[0 * DIN + ((q + (k << 3)) << 2)];
            float4 v1 = *(const float4*)&g_v[1 * DIN + ((q + (k << 3)) << 2)];
            float4 v2 = *(const float4*)&g_v[2 * DIN + ((q + (k << 3)) << 2)];
            p0 += dot4(x, v0); p1 += dot4(x, v1); p2 += dot4(x, v2);
        }
        #pragma unroll
        for (int o = 4; o; o >>= 1) {
            p0 += __shfl_xor_sync(0xffffffffu, p0, o);
            p1 += __shfl_xor_sync(0xffffffffu, p1, o);
            p2 += __shfl_xor_sync(0xffffffffu, p2, o);
        }
        if (q == 0) {
            snb[0 * 32 + node] = p0;
            snb[1 * 32 + node] = p1;
            snb[2 * 32 + node] = p2;
        }
    }

    // ---- s_self: 9 u-dots on node-0 row.
    // WARP-UNIFORM loop shape (fix for round-8 UB): every group runs exactly
    // 3 iterations with ui = min(g*3+t, 8); groups 2/3 redundantly recompute
    // ui=8 (same value, benign duplicate store) so all 32 lanes execute every
    // shfl_sync together.
    {
        float4 x0[4];
        #pragma unroll
        for (int k = 0; k < 4; ++k)
            x0[k] = ((const float4*)hb)[q + (k << 3)];   // node-0 row
        #pragma unroll
        for (int t = 0; t < 3; ++t) {
            int ui = g * 3 + t; if (ui > 8) ui = 8;
            const float* uvec = g_u + ui * DIN;
            float p = 0.f;
            #pragma unroll
            for (int k = 0; k < 4; ++k)
                p += dot4(x0[k], *(const float4*)&uvec[(q + (k << 3)) << 2]);
            #pragma unroll
            for (int o = 4; o; o >>= 1) p += __shfl_xor_sync(0xffffffffu, p, o);
            if (q == 0) sss[ui] = p;
        }
    }
    __syncwarp();

    // ---- dual register-resident softmax (lanes 1..15 ally, 16..31 opp) ----
    const float r0 = snb[0 * 32 + lane];
    const float r1 = snb[1 * 32 + lane];
    const float r2 = snb[2 * 32 + lane];
    float ss[9];
    #pragma unroll
    for (int k = 0; k < 9; ++k) ss[k] = sss[k];

    const float eb0 = (m0 || lane == 0) ? -INFINITY : r0;
    const float eb1 = (m1 || lane == 0) ? -INFINITY : r1;
    const float eb2 = (m2 || lane == 0) ? -INFINITY : r2;

    float mx = -INFINITY;
    #pragma unroll
    for (int i = 0; i < 3; ++i) {
        mx = fmaxf(mx, ss[i * 3 + 0] + eb0);
        mx = fmaxf(mx, ss[i * 3 + 1] + eb1);
        mx = fmaxf(mx, ss[i * 3 + 2] + eb2);
    }
    #pragma unroll
    for (int o = 8; o; o >>= 1) mx = fmaxf(mx, __shfl_xor_sync(0xffffffffu, mx, o));

    float s0 = 0.f, s1 = 0.f, s2 = 0.f;
    #pragma unroll
    for (int i = 0; i < 3; ++i) {
        s0 += __expf(ss[i * 3 + 0] + eb0 - mx);
        s1 += __expf(ss[i * 3 + 1] + eb1 - mx);
        s2 += __expf(ss[i * 3 + 2] + eb2 - mx);
    }
    float zs = s0 + s1 + s2;
    #pragma unroll
    for (int o = 8; o; o >>= 1) zs += __shfl_xor_sync(0xffffffffu, zs, o);
    // all-masked half -> zs NaN -> inv 0 -> weights 0 (matches reference)
    const float inv = (zs > 0.f) ? (1.f / zs) : 0.f;

    swt[0 * 32 + lane] = (lane == 0) ? (m0 ? 1.f : 0.f) : s0 * inv;
    swt[1 * 32 + lane] = (lane == 0) ? (m1 ? 1.f : 0.f) : s1 * inv;
    swt[2 * 32 + lane] = (lane == 0) ? (m2 ? 1.f : 0.f) : s2 * inv;
    __syncwarp();

    // ---- combine: re-read h (L1/L2 hot), coalesced, FMA into 3 accs ----
    const float4* hv = (const float4*)hb;
    float4 a0 = {0.f, 0.f, 0.f, 0.f}, a1 = a0, a2 = a0;
    #pragma unroll
    for (int n = 0; n < NNODES; ++n) {
        float4 x = hv[(n << 5) + lane];
        float w0 = swt[n], w1 = swt[32 + n], w2 = swt[64 + n];
        a0.x += w0 * x.x; a0.y += w0 * x.y; a0.z += w0 * x.z; a0.w += w0 * x.w;
        a1.x += w1 * x.x; a1.y += w1 * x.y; a1.z += w1 * x.z; a1.w += w1 * x.w;
        a2.x += w2 * x.x; a2.y += w2 * x.y; a2.z += w2 * x.z; a2.w += w2 * x.w;
    }
    float* gout = g_C + (size_t)b * (TT * DIN);
    const int d4 = lane << 2;
    *(float4*)&gout[0 * DIN + d4] = a0;
    *(float4*)&gout[1 * DIN + d4] = a1;
    *(float4*)&gout[2 * DIN + d4] = a2;
}

// ---------------------------------------------------------------------------
// k2: out = elu(C @ Wstack). M=8192, K=384, N=128. fp32 packed FFMA2.
// BM=BN=BK=64; block=256; grid=(128,2). Per-thread 2(M)x8(N).
// ---------------------------------------------------------------------------
#define GBM 64
#define GBN 64
#define GBK 64
#define APAD 3

#define FMA_F32X2(d, a, bb, c) \
    asm("fma.rn.f32x2 %0, %1, %2, %3;" : "=l"(d) : "l"(a), "l"(bb), "l"(c))
#define PACK_DUP(d, s) \
    asm("mov.b64 %0, {%1, %1};" : "=l"(d) : "r"(s))

__global__ __launch_bounds__(256) void k2_gemm_elu(
    const float* __restrict__ W, float* __restrict__ out)
{
    __shared__ float As[GBK][GBM + APAD];   // [k][m]
    __shared__ float Bs[GBK][GBN];          // [k][n]

    const int tid = threadIdx.x;
    const int bm0 = blockIdx.x * GBM;
    const int bn0 = blockIdx.y * GBN;
    const int tm0 = tid & 31;               // m = tm0 + 32*mi
    const int tn  = (tid >> 5) << 3;        // warp-uniform, 0..56

    unsigned long long acc[2][4];
    #pragma unroll
    for (int i = 0; i < 2; ++i)
        #pragma unroll
        for (int j = 0; j < 4; ++j) acc[i][j] = 0ull;

    const float* A = g_C;

    for (int k0 = 0; k0 < TT * DIN; k0 += GBK) {
        #pragma unroll
        for (int i = 0; i < 4; ++i) {       // A tile 64x64 -> transpose to As[k][m]
            int li = tid + i * 256;
            int r  = li >> 4;
            int c4 = (li & 15) << 2;
            float4 v = *(const float4*)&A[(size_t)(bm0 + r) * (TT * DIN) + k0 + c4];
            As[c4 + 0][r] = v.x; As[c4 + 1][r] = v.y;
            As[c4 + 2][r] = v.z; As[c4 + 3][r] = v.w;
        }
        #pragma unroll
        for (int i = 0; i < 4; ++i) {       // B tile 64x64 natural
            int li = tid + i * 256;
            int r  = li >> 4;
            int c4 = (li & 15) << 2;
            *(float4*)&Bs[r][c4] = *(const float4*)&W[(size_t)(k0 + r) * DIN + bn0 + c4];
        }
        __syncthreads();

        #pragma unroll 8
        for (int kk = 0; kk < GBK; ++kk) {
            unsigned long long ad[2];
            PACK_DUP(ad[0], __float_as_uint(As[kk][tm0]));
            PACK_DUP(ad[1], __float_as_uint(As[kk][tm0 + 32]));
            ulonglong2 b01 = *(const ulonglong2*)&Bs[kk][tn];
            ulonglong2 b23 = *(const ulonglong2*)&Bs[kk][tn + 4];
            unsigned long long bv[4] = {b01.x, b01.y, b23.x, b23.y};
            #pragma unroll
            for (int mi = 0; mi < 2; ++mi)
                #pragma unroll
                for (int jj = 0; jj < 4; ++jj)
                    FMA_F32X2(acc[mi][jj], ad[mi], bv[jj], acc[mi][jj]);
        }
        __syncthreads();
    }

    #pragma unroll
    for (int mi = 0; mi < 2; ++mi) {
        int m = bm0 + tm0 + 32 * mi;
        float o8[8];
        #pragma unroll
        for (int jj = 0; jj < 4; ++jj) {
            unsigned long long p = acc[mi][jj];
            o8[2 * jj]     = __uint_as_float((unsigned)(p & 0xffffffffull));
            o8[2 * jj + 1] = __uint_as_float((unsigned)(p >> 32));
        }
        #pragma unroll
        for (int q = 0; q < 8; ++q) {
            float x = o8[q];
            o8[q] = x > 0.f ? x : expm1f(x);
        }
        *(float4*)&out[(size_t)m * DIN + bn0 + tn]     = *(float4*)&o8[0];
        *(float4*)&out[(size_t)m * DIN + bn0 + tn + 4] = *(float4*)&o8[4];
    }
}

// ---------------------------------------------------------------------------
extern "C" void kernel_launch(void* const* d_in, const int* in_sizes, int n_in,
                              void* d_out, int out_size)
{
    const float* h = nullptr;
    const void*  mask = nullptr;
    const float* W = nullptr;
    const float* a = nullptr;

    for (int i = 0; i < n_in; ++i) {
        switch (in_sizes[i]) {
            case BATCH * NNODES * DIN: h    = (const float*)d_in[i]; break;   // 33554432
            case TT * BATCH * NNODES:  mask = d_in[i];               break;   // 786432
            case TT * DIN * HID:       W    = (const float*)d_in[i]; break;   // 49152
            case TT * 2 * HID:         a    = (const float*)d_in[i]; break;   // 768
            default: break; // scalars
        }
    }

    k0_precompute<<<49, 256>>>(W, a, (const unsigned*)mask);
    k1_scores_combine<<<BATCH / K1_WARPS, 32 * K1_WARPS>>>(h, mask);
    k2_gemm_elu<<<dim3(BATCH / GBM, DIN / GBN), 256>>>(W, (float*)d_out);
}